// round 14
// baseline (speedup 1.0000x reference)
#include <cuda_runtime.h>
#include <cuda_fp16.h>
#include <cstdint>

#define BHN 16
#define SEQ 4096
#define HD 64
#define BM 128
#define BN 64
#define NTHREADS 128
#define KPITCH 72   // smem row pitch in halves (144B rows -> conflict-free LDSM)
#define NT (SEQ / BN)
#define SPLIT 4
#define HT (NT / SPLIT)   // key-tiles per pass-B CTA

// fp16 scratch copies of K and V (converted once per launch)
__device__ __half2 Ksc[BHN * SEQ * HD / 2];
__device__ __half2 Vsc[BHN * SEQ * HD / 2];
// per-row -log2(rowsum)
__device__ float LinvG[BHN * SEQ];
// partial O per key-split
__device__ float OPart[SPLIT * BHN * SEQ * HD];

__device__ __forceinline__ float ex2f(float x) {
    float y;
    asm("ex2.approx.f32 %0, %1;" : "=f"(y) : "f"(x));
    return y;
}

__device__ __forceinline__ uint32_t h2ex2(uint32_t x) {
    uint32_t y;
    asm("ex2.approx.f16x2 %0, %1;" : "=r"(y) : "r"(x));
    return y;
}

__device__ __forceinline__ uint32_t packh2(float a, float b) {
    __half2 t = __floats2half2_rn(a, b);
    return reinterpret_cast<uint32_t&>(t);
}

__device__ __forceinline__ uint32_t hadd2u(uint32_t a, uint32_t b) {
    __half2 r = __hadd2(reinterpret_cast<__half2&>(a), reinterpret_cast<__half2&>(b));
    return reinterpret_cast<uint32_t&>(r);
}

__device__ __forceinline__ void mma16816(float c[4], const uint32_t a[4],
                                         uint32_t b0, uint32_t b1) {
    asm volatile(
        "mma.sync.aligned.m16n8k16.row.col.f32.f16.f16.f32 "
        "{%0,%1,%2,%3},{%4,%5,%6,%7},{%8,%9},{%0,%1,%2,%3};"
        : "+f"(c[0]), "+f"(c[1]), "+f"(c[2]), "+f"(c[3])
        : "r"(a[0]), "r"(a[1]), "r"(a[2]), "r"(a[3]), "r"(b0), "r"(b1));
}

__device__ __forceinline__ void mma16816h(uint32_t c[2], const uint32_t a[4],
                                          uint32_t b0, uint32_t b1) {
    asm volatile(
        "mma.sync.aligned.m16n8k16.row.col.f16.f16.f16.f16 "
        "{%0,%1},{%2,%3,%4,%5},{%6,%7},{%0,%1};"
        : "+r"(c[0]), "+r"(c[1])
        : "r"(a[0]), "r"(a[1]), "r"(a[2]), "r"(a[3]), "r"(b0), "r"(b1));
}

__device__ __forceinline__ void ldsm_x4(uint32_t& r0, uint32_t& r1, uint32_t& r2,
                                        uint32_t& r3, uint32_t addr) {
    asm volatile("ldmatrix.sync.aligned.m8n8.x4.shared.b16 {%0,%1,%2,%3},[%4];"
                 : "=r"(r0), "=r"(r1), "=r"(r2), "=r"(r3) : "r"(addr));
}

__device__ __forceinline__ void ldsm_x4_t(uint32_t& r0, uint32_t& r1, uint32_t& r2,
                                          uint32_t& r3, uint32_t addr) {
    asm volatile("ldmatrix.sync.aligned.m8n8.x4.trans.shared.b16 {%0,%1,%2,%3},[%4];"
                 : "=r"(r0), "=r"(r1), "=r"(r2), "=r"(r3) : "r"(addr));
}

__device__ __forceinline__ void cpasync16(uint32_t dst, const void* src) {
    asm volatile("cp.async.cg.shared.global [%0],[%1],16;" :: "r"(dst), "l"(src));
}
__device__ __forceinline__ void cp_commit() {
    asm volatile("cp.async.commit_group;");
}
template <int N>
__device__ __forceinline__ void cp_wait() {
    asm volatile("cp.async.wait_group %0;" :: "n"(N));
}

// prefetch one [BN x HD] fp16 tile, rows permuted within each 16-key group.
__device__ __forceinline__ void prefetch_tile(uint32_t dstbase, const __half* src,
                                              int tid) {
#pragma unroll
    for (int t = 0; t < 4; ++t) {
        int i = tid + t * NTHREADS;
        int r = i >> 3;
        int c8 = (i & 7) << 3;
        int s = r & 15;
        int a = ((s & 6) << 1) | ((s & 8) >> 2) | (s & 1);
        int srcr = (r & 48) | a;
        cpasync16(dstbase + (uint32_t)((r * KPITCH + c8) * 2), src + srcr * HD + c8);
    }
}

// ---------------- pre-conversion kernel ----------------
__global__ void __launch_bounds__(256)
convert_kernel(const float* __restrict__ K, const float* __restrict__ V) {
    const int n4 = BHN * SEQ * HD / 4;
    int i = blockIdx.x * blockDim.x + threadIdx.x;
    if (i < n4) {
        float4 f = reinterpret_cast<const float4*>(K)[i];
        Ksc[2 * i] = __floats2half2_rn(f.x, f.y);
        Ksc[2 * i + 1] = __floats2half2_rn(f.z, f.w);
    } else {
        int j = i - n4;
        float4 f = reinterpret_cast<const float4*>(V)[j];
        Vsc[2 * j] = __floats2half2_rn(f.x, f.y);
        Vsc[2 * j + 1] = __floats2half2_rn(f.z, f.w);
    }
}

// ---------------- PASS A kernel: row sums via f16-accum MMA (single wave) -----
__global__ void __launch_bounds__(NTHREADS, 5)
rowsum_kernel(const float* __restrict__ Qg) {
    __shared__ __half Kb[2][BN * KPITCH];

    const int bh = blockIdx.y;
    const float* Qb = Qg + (size_t)bh * SEQ * HD;
    const __half* Kb16 = reinterpret_cast<const __half*>(Ksc) + (size_t)bh * SEQ * HD;

    const int tid = threadIdx.x;
    const int warp = tid >> 5;
    const int lane = tid & 31;
    const int g = lane >> 2;
    const int qq = lane & 3;
    const int row0 = blockIdx.x * BM + warp * 32;

    const uint32_t bK0 = (uint32_t)__cvta_generic_to_shared(&Kb[0][0]);
    const uint32_t bK1 = (uint32_t)__cvta_generic_to_shared(&Kb[1][0]);

    const int qk_r = (lane & 7) + ((lane & 16) ? 8 : 0);
    const int qk_c = (lane & 8) ? 8 : 0;
    const uint32_t offK = (uint32_t)((qk_r * KPITCH + qk_c) * 2);
    const uint32_t NPOFF = 16 * KPITCH * 2;

    const float SC = 0.1803368801111244f;

    uint32_t qh[2][4][4];
#pragma unroll
    for (int rf = 0; rf < 2; ++rf)
#pragma unroll
        for (int kc = 0; kc < 4; ++kc)
#pragma unroll
            for (int p = 0; p < 4; ++p) {
                int r = row0 + rf * 16 + g + (p & 1) * 8;
                int d = kc * 16 + (p >> 1) * 8 + qq * 2;
                float2 f = *reinterpret_cast<const float2*>(Qb + (size_t)r * HD + d);
                qh[rf][kc][p] = packh2(f.x * SC, f.y * SC);
            }

    float rs[2][2] = {};
    prefetch_tile(bK0, Kb16, tid);
    cp_commit();
    for (int kt = 0; kt < NT; ++kt) {
        if (kt + 1 < NT) {
            prefetch_tile((kt & 1) ? bK0 : bK1, Kb16 + (size_t)(kt + 1) * BN * HD, tid);
            cp_commit();
            cp_wait<1>();
        } else {
            cp_wait<0>();
        }
        __syncthreads();
        const uint32_t aK = ((kt & 1) ? bK1 : bK0) + offK;
        uint32_t acc[2][2] = {{0, 0}, {0, 0}};
#pragma unroll
        for (int np = 0; np < 4; ++np) {
            uint32_t h[4][4];
#pragma unroll
            for (int kc = 0; kc < 4; ++kc)
                ldsm_x4(h[kc][0], h[kc][1], h[kc][2], h[kc][3],
                        aK + np * NPOFF + kc * 32);
#pragma unroll
            for (int rf = 0; rf < 2; ++rf) {
                uint32_t ca[2] = {0, 0}, cb[2] = {0, 0};
#pragma unroll
                for (int kc = 0; kc < 4; ++kc) {
                    mma16816h(ca, qh[rf][kc], h[kc][0], h[kc][1]);
                    mma16816h(cb, qh[rf][kc], h[kc][2], h[kc][3]);
                }
                acc[rf][0] = hadd2u(acc[rf][0], hadd2u(h2ex2(ca[0]), h2ex2(cb[0])));
                acc[rf][1] = hadd2u(acc[rf][1], hadd2u(h2ex2(ca[1]), h2ex2(cb[1])));
            }
        }
#pragma unroll
        for (int rf = 0; rf < 2; ++rf) {
            float2 f0 = __half22float2(reinterpret_cast<__half2&>(acc[rf][0]));
            float2 f1 = __half22float2(reinterpret_cast<__half2&>(acc[rf][1]));
            rs[rf][0] += f0.x + f0.y;
            rs[rf][1] += f1.x + f1.y;
        }
        __syncthreads();
    }
#pragma unroll
    for (int rf = 0; rf < 2; ++rf)
#pragma unroll
        for (int h = 0; h < 2; ++h) {
            float v = rs[rf][h];
            v += __shfl_xor_sync(0xffffffffu, v, 1);
            v += __shfl_xor_sync(0xffffffffu, v, 2);
            if (qq == 0)
                LinvG[bh * SEQ + row0 + rf * 16 + g + h * 8] = -__log2f(v);
        }
}

// ---------------- PASS B kernel: key-split quarters ----------
__global__ void __launch_bounds__(NTHREADS, 3)
attn_kernel(const float* __restrict__ Qg, float* __restrict__ out) {
    __shared__ __half Kb[2][BN * KPITCH];
    __shared__ __half Vb[2][BN * KPITCH];

    const int bh = blockIdx.y;
    const int kz = blockIdx.z;          // key-split index
    const int kt0 = kz * HT;
    const float* Qb = Qg + (size_t)bh * SEQ * HD;
    const __half* Kb16 = reinterpret_cast<const __half*>(Ksc) + (size_t)bh * SEQ * HD +
                         (size_t)kt0 * BN * HD;
    const __half* Vb16 = reinterpret_cast<const __half*>(Vsc) + (size_t)bh * SEQ * HD +
                         (size_t)kt0 * BN * HD;
    float* OPb = OPart + ((size_t)kz * BHN + bh) * SEQ * HD;
    float* Ab = out + (size_t)BHN * SEQ * HD + (size_t)bh * SEQ * SEQ;

    const int tid = threadIdx.x;
    const int warp = tid >> 5;
    const int lane = tid & 31;
    const int g = lane >> 2;
    const int qq = lane & 3;
    const int row0 = blockIdx.x * BM + warp * 32;

    const uint32_t bK0 = (uint32_t)__cvta_generic_to_shared(&Kb[0][0]);
    const uint32_t bK1 = (uint32_t)__cvta_generic_to_shared(&Kb[1][0]);
    const uint32_t bV0 = (uint32_t)__cvta_generic_to_shared(&Vb[0][0]);
    const uint32_t bV1 = (uint32_t)__cvta_generic_to_shared(&Vb[1][0]);

    const int qk_r = (lane & 7) + ((lane & 16) ? 8 : 0);
    const int qk_c = (lane & 8) ? 8 : 0;
    const uint32_t offK = (uint32_t)((qk_r * KPITCH + qk_c) * 2);
    const int v_r = (lane & 7) + ((lane & 8) ? 8 : 0);
    const int v_c = (lane & 16) ? 8 : 0;
    const uint32_t offV = (uint32_t)((v_r * KPITCH + v_c) * 2);
    const uint32_t NPOFF = 16 * KPITCH * 2;

    const float SC = 0.1803368801111244f;

    uint32_t qh[2][4][4];
#pragma unroll
    for (int rf = 0; rf < 2; ++rf)
#pragma unroll
        for (int kc = 0; kc < 4; ++kc)
#pragma unroll
            for (int p = 0; p < 4; ++p) {
                int r = row0 + rf * 16 + g + (p & 1) * 8;
                int d = kc * 16 + (p >> 1) * 8 + qq * 2;
                float2 f = *reinterpret_cast<const float2*>(Qb + (size_t)r * HD + d);
                qh[rf][kc][p] = packh2(f.x * SC, f.y * SC);
            }

    float linv[2][2];
#pragma unroll
    for (int rf = 0; rf < 2; ++rf)
#pragma unroll
        for (int h = 0; h < 2; ++h)
            linv[rf][h] = LinvG[bh * SEQ + row0 + rf * 16 + g + h * 8];

    float o[2][8][4] = {};
    prefetch_tile(bK0, Kb16, tid);
    prefetch_tile(bV0, Vb16, tid);
    cp_commit();
    for (int kt = 0; kt < HT; ++kt) {
        if (kt + 1 < HT) {
            const uint32_t dK = (kt & 1) ? bK0 : bK1;
            const uint32_t dV = (kt & 1) ? bV0 : bV1;
            prefetch_tile(dK, Kb16 + (size_t)(kt + 1) * BN * HD, tid);
            prefetch_tile(dV, Vb16 + (size_t)(kt + 1) * BN * HD, tid);
            cp_commit();
            cp_wait<1>();
        } else {
            cp_wait<0>();
        }
        __syncthreads();
        const uint32_t aK = ((kt & 1) ? bK1 : bK0) + offK;
        const uint32_t aV = ((kt & 1) ? bV1 : bV0) + offV;

#pragma unroll
        for (int np = 0; np < 4; ++np) {
            uint32_t h[4][4];
#pragma unroll
            for (int kc = 0; kc < 4; ++kc)
                ldsm_x4(h[kc][0], h[kc][1], h[kc][2], h[kc][3],
                        aK + np * NPOFF + kc * 32);
            float ca[2][4] = {}, cb[2][4] = {};
#pragma unroll
            for (int rf = 0; rf < 2; ++rf)
#pragma unroll
                for (int kc = 0; kc < 4; ++kc) {
                    mma16816(ca[rf], qh[rf][kc], h[kc][0], h[kc][1]);
                    mma16816(cb[rf], qh[rf][kc], h[kc][2], h[kc][3]);
                }

            uint32_t ah[2][4];
#pragma unroll
            for (int rf = 0; rf < 2; ++rf) {
                const float l0 = linv[rf][0], l1 = linv[rf][1];
                ca[rf][0] = ex2f(ca[rf][0] + l0);
                ca[rf][1] = ex2f(ca[rf][1] + l0);
                ca[rf][2] = ex2f(ca[rf][2] + l1);
                ca[rf][3] = ex2f(ca[rf][3] + l1);
                cb[rf][0] = ex2f(cb[rf][0] + l0);
                cb[rf][1] = ex2f(cb[rf][1] + l0);
                cb[rf][2] = ex2f(cb[rf][2] + l1);
                cb[rf][3] = ex2f(cb[rf][3] + l1);
                float* arow0 = Ab + (size_t)(row0 + rf * 16 + g) * SEQ +
                               (kt0 + kt) * BN + 16 * np + qq * 4;
                __stcs(reinterpret_cast<float4*>(arow0),
                       make_float4(ca[rf][0], ca[rf][1], cb[rf][0], cb[rf][1]));
                __stcs(reinterpret_cast<float4*>(arow0 + 8 * SEQ),
                       make_float4(ca[rf][2], ca[rf][3], cb[rf][2], cb[rf][3]));
                ah[rf][0] = packh2(ca[rf][0], ca[rf][1]);
                ah[rf][1] = packh2(ca[rf][2], ca[rf][3]);
                ah[rf][2] = packh2(cb[rf][0], cb[rf][1]);
                ah[rf][3] = packh2(cb[rf][2], cb[rf][3]);
            }

#pragma unroll
            for (int nd = 0; nd < 4; ++nd) {
                uint32_t v0, v1, v2, v3;
                ldsm_x4_t(v0, v1, v2, v3, aV + np * NPOFF + nd * 32);
#pragma unroll
                for (int rf = 0; rf < 2; ++rf) {
                    mma16816(o[rf][2 * nd], ah[rf], v0, v1);
                    mma16816(o[rf][2 * nd + 1], ah[rf], v2, v3);
                }
            }
        }
        __syncthreads();
    }

    // ---- write partial O ----
#pragma unroll
    for (int rf = 0; rf < 2; ++rf)
#pragma unroll
        for (int nt = 0; nt < 8; ++nt) {
            int col = nt * 8 + qq * 2;
            int r = row0 + rf * 16 + g;
            *reinterpret_cast<float2*>(OPb + (size_t)r * HD + col) =
                make_float2(o[rf][nt][0], o[rf][nt][1]);
            *reinterpret_cast<float2*>(OPb + (size_t)(r + 8) * HD + col) =
                make_float2(o[rf][nt][2], o[rf][nt][3]);
        }
}

// ---------------- O reduce: O = sum of SPLIT partials (fixed order) ----------
__global__ void __launch_bounds__(256)
reduce_kernel(float* __restrict__ out) {
    const int n4 = BHN * SEQ * HD / 4;
    int i = blockIdx.x * blockDim.x + threadIdx.x;
    if (i < n4) {
        const float4* a = reinterpret_cast<const float4*>(OPart);
        float4 s = a[i];
#pragma unroll
        for (int p = 1; p < SPLIT; ++p) {
            float4 y = a[i + (size_t)p * n4];
            s.x += y.x; s.y += y.y; s.z += y.z; s.w += y.w;
        }
        reinterpret_cast<float4*>(out)[i] = s;
    }
}

extern "C" void kernel_launch(void* const* d_in, const int* in_sizes, int n_in,
                              void* d_out, int out_size) {
    const float* q = (const float*)d_in[0];
    const float* k = (const float*)d_in[1];
    const float* v = (const float*)d_in[2];
    (void)in_sizes; (void)n_in; (void)out_size;
    const int n4 = BHN * SEQ * HD / 4;
    convert_kernel<<<(2 * n4) / 256, 256>>>(k, v);
    dim3 gridA(SEQ / BM, BHN);
    rowsum_kernel<<<gridA, NTHREADS>>>(q);
    dim3 gridB(SEQ / BM, BHN, SPLIT);
    attn_kernel<<<gridB, NTHREADS>>>(q, (float*)d_out);
    reduce_kernel<<<(n4 + 255) / 256, 256>>>((float*)d_out);
}

// round 15
// speedup vs baseline: 1.0537x; 1.0537x over previous
#include <cuda_runtime.h>
#include <cuda_fp16.h>
#include <cstdint>

#define BHN 16
#define SEQ 4096
#define HD 64
#define BM 128
#define BN 64
#define NTHREADS 128
#define KPITCH 72   // smem row pitch in halves (144B rows -> conflict-free LDSM)
#define NT (SEQ / BN)
#define SPLIT 2
#define HT (NT / SPLIT)   // key-tiles per pass-B CTA
#define KS 4
#define RT (NT / KS)      // key-tiles per rowsum CTA

// fp16 scratch copies of K and V (converted once per launch)
__device__ __half2 Ksc[BHN * SEQ * HD / 2];
__device__ __half2 Vsc[BHN * SEQ * HD / 2];
// rowsum partials and combined -log2(rowsum)
__device__ float RsP[KS * BHN * SEQ];
__device__ float LinvG[BHN * SEQ];
// partial O per key-split
__device__ float OPart[SPLIT * BHN * SEQ * HD];

__device__ __forceinline__ float ex2f(float x) {
    float y;
    asm("ex2.approx.f32 %0, %1;" : "=f"(y) : "f"(x));
    return y;
}

__device__ __forceinline__ uint32_t h2ex2(uint32_t x) {
    uint32_t y;
    asm("ex2.approx.f16x2 %0, %1;" : "=r"(y) : "r"(x));
    return y;
}

__device__ __forceinline__ uint32_t packh2(float a, float b) {
    __half2 t = __floats2half2_rn(a, b);
    return reinterpret_cast<uint32_t&>(t);
}

__device__ __forceinline__ uint32_t hadd2u(uint32_t a, uint32_t b) {
    __half2 r = __hadd2(reinterpret_cast<__half2&>(a), reinterpret_cast<__half2&>(b));
    return reinterpret_cast<uint32_t&>(r);
}

__device__ __forceinline__ void mma16816(float c[4], const uint32_t a[4],
                                         uint32_t b0, uint32_t b1) {
    asm volatile(
        "mma.sync.aligned.m16n8k16.row.col.f32.f16.f16.f32 "
        "{%0,%1,%2,%3},{%4,%5,%6,%7},{%8,%9},{%0,%1,%2,%3};"
        : "+f"(c[0]), "+f"(c[1]), "+f"(c[2]), "+f"(c[3])
        : "r"(a[0]), "r"(a[1]), "r"(a[2]), "r"(a[3]), "r"(b0), "r"(b1));
}

__device__ __forceinline__ void mma16816h(uint32_t c[2], const uint32_t a[4],
                                          uint32_t b0, uint32_t b1) {
    asm volatile(
        "mma.sync.aligned.m16n8k16.row.col.f16.f16.f16.f16 "
        "{%0,%1},{%2,%3,%4,%5},{%6,%7},{%0,%1};"
        : "+r"(c[0]), "+r"(c[1])
        : "r"(a[0]), "r"(a[1]), "r"(a[2]), "r"(a[3]), "r"(b0), "r"(b1));
}

__device__ __forceinline__ void ldsm_x4(uint32_t& r0, uint32_t& r1, uint32_t& r2,
                                        uint32_t& r3, uint32_t addr) {
    asm volatile("ldmatrix.sync.aligned.m8n8.x4.shared.b16 {%0,%1,%2,%3},[%4];"
                 : "=r"(r0), "=r"(r1), "=r"(r2), "=r"(r3) : "r"(addr));
}

__device__ __forceinline__ void ldsm_x4_t(uint32_t& r0, uint32_t& r1, uint32_t& r2,
                                          uint32_t& r3, uint32_t addr) {
    asm volatile("ldmatrix.sync.aligned.m8n8.x4.trans.shared.b16 {%0,%1,%2,%3},[%4];"
                 : "=r"(r0), "=r"(r1), "=r"(r2), "=r"(r3) : "r"(addr));
}

__device__ __forceinline__ void cpasync16(uint32_t dst, const void* src) {
    asm volatile("cp.async.cg.shared.global [%0],[%1],16;" :: "r"(dst), "l"(src));
}
__device__ __forceinline__ void cp_commit() {
    asm volatile("cp.async.commit_group;");
}
template <int N>
__device__ __forceinline__ void cp_wait() {
    asm volatile("cp.async.wait_group %0;" :: "n"(N));
}

// prefetch one [BN x HD] fp16 tile, rows permuted within each 16-key group.
__device__ __forceinline__ void prefetch_tile(uint32_t dstbase, const __half* src,
                                              int tid) {
#pragma unroll
    for (int t = 0; t < 4; ++t) {
        int i = tid + t * NTHREADS;
        int r = i >> 3;
        int c8 = (i & 7) << 3;
        int s = r & 15;
        int a = ((s & 6) << 1) | ((s & 8) >> 2) | (s & 1);
        int srcr = (r & 48) | a;
        cpasync16(dstbase + (uint32_t)((r * KPITCH + c8) * 2), src + srcr * HD + c8);
    }
}

// ---------------- pre-conversion kernel ----------------
__global__ void __launch_bounds__(256)
convert_kernel(const float* __restrict__ K, const float* __restrict__ V) {
    const int n4 = BHN * SEQ * HD / 4;
    int i = blockIdx.x * blockDim.x + threadIdx.x;
    if (i < n4) {
        float4 f = reinterpret_cast<const float4*>(K)[i];
        Ksc[2 * i] = __floats2half2_rn(f.x, f.y);
        Ksc[2 * i + 1] = __floats2half2_rn(f.z, f.w);
    } else {
        int j = i - n4;
        float4 f = reinterpret_cast<const float4*>(V)[j];
        Vsc[2 * j] = __floats2half2_rn(f.x, f.y);
        Vsc[2 * j + 1] = __floats2half2_rn(f.z, f.w);
    }
}

// ---------------- PASS A kernel: partial row sums, KS=4 key-split -------------
__global__ void __launch_bounds__(NTHREADS, 5)
rowsum_kernel(const float* __restrict__ Qg) {
    __shared__ __half Kb[2][BN * KPITCH];

    const int bh = blockIdx.y;
    const int kz = blockIdx.z;
    const float* Qb = Qg + (size_t)bh * SEQ * HD;
    const __half* Kb16 = reinterpret_cast<const __half*>(Ksc) + (size_t)bh * SEQ * HD +
                         (size_t)kz * RT * BN * HD;

    const int tid = threadIdx.x;
    const int warp = tid >> 5;
    const int lane = tid & 31;
    const int g = lane >> 2;
    const int qq = lane & 3;
    const int row0 = blockIdx.x * BM + warp * 32;

    const uint32_t bK0 = (uint32_t)__cvta_generic_to_shared(&Kb[0][0]);
    const uint32_t bK1 = (uint32_t)__cvta_generic_to_shared(&Kb[1][0]);

    const int qk_r = (lane & 7) + ((lane & 16) ? 8 : 0);
    const int qk_c = (lane & 8) ? 8 : 0;
    const uint32_t offK = (uint32_t)((qk_r * KPITCH + qk_c) * 2);
    const uint32_t NPOFF = 16 * KPITCH * 2;

    const float SC = 0.1803368801111244f;

    uint32_t qh[2][4][4];
#pragma unroll
    for (int rf = 0; rf < 2; ++rf)
#pragma unroll
        for (int kc = 0; kc < 4; ++kc)
#pragma unroll
            for (int p = 0; p < 4; ++p) {
                int r = row0 + rf * 16 + g + (p & 1) * 8;
                int d = kc * 16 + (p >> 1) * 8 + qq * 2;
                float2 f = *reinterpret_cast<const float2*>(Qb + (size_t)r * HD + d);
                qh[rf][kc][p] = packh2(f.x * SC, f.y * SC);
            }

    float rs[2][2] = {};
    prefetch_tile(bK0, Kb16, tid);
    cp_commit();
    for (int kt = 0; kt < RT; ++kt) {
        if (kt + 1 < RT) {
            prefetch_tile((kt & 1) ? bK0 : bK1, Kb16 + (size_t)(kt + 1) * BN * HD, tid);
            cp_commit();
            cp_wait<1>();
        } else {
            cp_wait<0>();
        }
        __syncthreads();
        const uint32_t aK = ((kt & 1) ? bK1 : bK0) + offK;
        uint32_t acc[2][2] = {{0, 0}, {0, 0}};
#pragma unroll
        for (int np = 0; np < 4; ++np) {
            uint32_t h[4][4];
#pragma unroll
            for (int kc = 0; kc < 4; ++kc)
                ldsm_x4(h[kc][0], h[kc][1], h[kc][2], h[kc][3],
                        aK + np * NPOFF + kc * 32);
#pragma unroll
            for (int rf = 0; rf < 2; ++rf) {
                uint32_t ca[2] = {0, 0}, cb[2] = {0, 0};
#pragma unroll
                for (int kc = 0; kc < 4; ++kc) {
                    mma16816h(ca, qh[rf][kc], h[kc][0], h[kc][1]);
                    mma16816h(cb, qh[rf][kc], h[kc][2], h[kc][3]);
                }
                acc[rf][0] = hadd2u(acc[rf][0], hadd2u(h2ex2(ca[0]), h2ex2(cb[0])));
                acc[rf][1] = hadd2u(acc[rf][1], hadd2u(h2ex2(ca[1]), h2ex2(cb[1])));
            }
        }
#pragma unroll
        for (int rf = 0; rf < 2; ++rf) {
            float2 f0 = __half22float2(reinterpret_cast<__half2&>(acc[rf][0]));
            float2 f1 = __half22float2(reinterpret_cast<__half2&>(acc[rf][1]));
            rs[rf][0] += f0.x + f0.y;
            rs[rf][1] += f1.x + f1.y;
        }
        __syncthreads();
    }
#pragma unroll
    for (int rf = 0; rf < 2; ++rf)
#pragma unroll
        for (int h = 0; h < 2; ++h) {
            float v = rs[rf][h];
            v += __shfl_xor_sync(0xffffffffu, v, 1);
            v += __shfl_xor_sync(0xffffffffu, v, 2);
            if (qq == 0)
                RsP[((size_t)kz * BHN + bh) * SEQ + row0 + rf * 16 + g + h * 8] = v;
        }
}

// ------------- combine KS partial rowsums into -log2(rowsum), fixed order -----
__global__ void __launch_bounds__(256)
linv_kernel() {
    const int n = BHN * SEQ;
    int i = blockIdx.x * blockDim.x + threadIdx.x;
    if (i < n) {
        float s = RsP[i];
#pragma unroll
        for (int p = 1; p < KS; ++p) s += RsP[i + p * n];
        LinvG[i] = -__log2f(s);
    }
}

// ---------------- PASS B kernel: key-split halves ----------
__global__ void __launch_bounds__(NTHREADS, 3)
attn_kernel(const float* __restrict__ Qg, float* __restrict__ out) {
    __shared__ __half Kb[2][BN * KPITCH];
    __shared__ __half Vb[2][BN * KPITCH];

    const int bh = blockIdx.y;
    const int kz = blockIdx.z;          // key-split index
    const int kt0 = kz * HT;
    const float* Qb = Qg + (size_t)bh * SEQ * HD;
    const __half* Kb16 = reinterpret_cast<const __half*>(Ksc) + (size_t)bh * SEQ * HD +
                         (size_t)kt0 * BN * HD;
    const __half* Vb16 = reinterpret_cast<const __half*>(Vsc) + (size_t)bh * SEQ * HD +
                         (size_t)kt0 * BN * HD;
    float* OPb = OPart + ((size_t)kz * BHN + bh) * SEQ * HD;
    float* Ab = out + (size_t)BHN * SEQ * HD + (size_t)bh * SEQ * SEQ;

    const int tid = threadIdx.x;
    const int warp = tid >> 5;
    const int lane = tid & 31;
    const int g = lane >> 2;
    const int qq = lane & 3;
    const int row0 = blockIdx.x * BM + warp * 32;

    const uint32_t bK0 = (uint32_t)__cvta_generic_to_shared(&Kb[0][0]);
    const uint32_t bK1 = (uint32_t)__cvta_generic_to_shared(&Kb[1][0]);
    const uint32_t bV0 = (uint32_t)__cvta_generic_to_shared(&Vb[0][0]);
    const uint32_t bV1 = (uint32_t)__cvta_generic_to_shared(&Vb[1][0]);

    const int qk_r = (lane & 7) + ((lane & 16) ? 8 : 0);
    const int qk_c = (lane & 8) ? 8 : 0;
    const uint32_t offK = (uint32_t)((qk_r * KPITCH + qk_c) * 2);
    const int v_r = (lane & 7) + ((lane & 8) ? 8 : 0);
    const int v_c = (lane & 16) ? 8 : 0;
    const uint32_t offV = (uint32_t)((v_r * KPITCH + v_c) * 2);
    const uint32_t NPOFF = 16 * KPITCH * 2;

    const float SC = 0.1803368801111244f;

    uint32_t qh[2][4][4];
#pragma unroll
    for (int rf = 0; rf < 2; ++rf)
#pragma unroll
        for (int kc = 0; kc < 4; ++kc)
#pragma unroll
            for (int p = 0; p < 4; ++p) {
                int r = row0 + rf * 16 + g + (p & 1) * 8;
                int d = kc * 16 + (p >> 1) * 8 + qq * 2;
                float2 f = *reinterpret_cast<const float2*>(Qb + (size_t)r * HD + d);
                qh[rf][kc][p] = packh2(f.x * SC, f.y * SC);
            }

    float linv[2][2];
#pragma unroll
    for (int rf = 0; rf < 2; ++rf)
#pragma unroll
        for (int h = 0; h < 2; ++h)
            linv[rf][h] = LinvG[bh * SEQ + row0 + rf * 16 + g + h * 8];

    float o[2][8][4] = {};
    prefetch_tile(bK0, Kb16, tid);
    prefetch_tile(bV0, Vb16, tid);
    cp_commit();
    for (int kt = 0; kt < HT; ++kt) {
        if (kt + 1 < HT) {
            const uint32_t dK = (kt & 1) ? bK0 : bK1;
            const uint32_t dV = (kt & 1) ? bV0 : bV1;
            prefetch_tile(dK, Kb16 + (size_t)(kt + 1) * BN * HD, tid);
            prefetch_tile(dV, Vb16 + (size_t)(kt + 1) * BN * HD, tid);
            cp_commit();
            cp_wait<1>();
        } else {
            cp_wait<0>();
        }
        __syncthreads();
        const uint32_t aK = ((kt & 1) ? bK1 : bK0) + offK;
        const uint32_t aV = ((kt & 1) ? bV1 : bV0) + offV;

#pragma unroll
        for (int np = 0; np < 4; ++np) {
            uint32_t h[4][4];
#pragma unroll
            for (int kc = 0; kc < 4; ++kc)
                ldsm_x4(h[kc][0], h[kc][1], h[kc][2], h[kc][3],
                        aK + np * NPOFF + kc * 32);
            float ca[2][4] = {}, cb[2][4] = {};
#pragma unroll
            for (int rf = 0; rf < 2; ++rf)
#pragma unroll
                for (int kc = 0; kc < 4; ++kc) {
                    mma16816(ca[rf], qh[rf][kc], h[kc][0], h[kc][1]);
                    mma16816(cb[rf], qh[rf][kc], h[kc][2], h[kc][3]);
                }

            uint32_t ah[2][4];
#pragma unroll
            for (int rf = 0; rf < 2; ++rf) {
                const float l0 = linv[rf][0], l1 = linv[rf][1];
                ca[rf][0] = ex2f(ca[rf][0] + l0);
                ca[rf][1] = ex2f(ca[rf][1] + l0);
                ca[rf][2] = ex2f(ca[rf][2] + l1);
                ca[rf][3] = ex2f(ca[rf][3] + l1);
                cb[rf][0] = ex2f(cb[rf][0] + l0);
                cb[rf][1] = ex2f(cb[rf][1] + l0);
                cb[rf][2] = ex2f(cb[rf][2] + l1);
                cb[rf][3] = ex2f(cb[rf][3] + l1);
                float* arow0 = Ab + (size_t)(row0 + rf * 16 + g) * SEQ +
                               (kt0 + kt) * BN + 16 * np + qq * 4;
                __stcs(reinterpret_cast<float4*>(arow0),
                       make_float4(ca[rf][0], ca[rf][1], cb[rf][0], cb[rf][1]));
                __stcs(reinterpret_cast<float4*>(arow0 + 8 * SEQ),
                       make_float4(ca[rf][2], ca[rf][3], cb[rf][2], cb[rf][3]));
                ah[rf][0] = packh2(ca[rf][0], ca[rf][1]);
                ah[rf][1] = packh2(ca[rf][2], ca[rf][3]);
                ah[rf][2] = packh2(cb[rf][0], cb[rf][1]);
                ah[rf][3] = packh2(cb[rf][2], cb[rf][3]);
            }

#pragma unroll
            for (int nd = 0; nd < 4; ++nd) {
                uint32_t v0, v1, v2, v3;
                ldsm_x4_t(v0, v1, v2, v3, aV + np * NPOFF + nd * 32);
#pragma unroll
                for (int rf = 0; rf < 2; ++rf) {
                    mma16816(o[rf][2 * nd], ah[rf], v0, v1);
                    mma16816(o[rf][2 * nd + 1], ah[rf], v2, v3);
                }
            }
        }
        __syncthreads();
    }

    // ---- write partial O ----
#pragma unroll
    for (int rf = 0; rf < 2; ++rf)
#pragma unroll
        for (int nt = 0; nt < 8; ++nt) {
            int col = nt * 8 + qq * 2;
            int r = row0 + rf * 16 + g;
            *reinterpret_cast<float2*>(OPb + (size_t)r * HD + col) =
                make_float2(o[rf][nt][0], o[rf][nt][1]);
            *reinterpret_cast<float2*>(OPb + (size_t)(r + 8) * HD + col) =
                make_float2(o[rf][nt][2], o[rf][nt][3]);
        }
}

// ---------------- O reduce: O = sum of SPLIT partials (fixed order) ----------
__global__ void __launch_bounds__(256)
reduce_kernel(float* __restrict__ out) {
    const int n4 = BHN * SEQ * HD / 4;
    int i = blockIdx.x * blockDim.x + threadIdx.x;
    if (i < n4) {
        const float4* a = reinterpret_cast<const float4*>(OPart);
        float4 s = a[i];
#pragma unroll
        for (int p = 1; p < SPLIT; ++p) {
            float4 y = a[i + (size_t)p * n4];
            s.x += y.x; s.y += y.y; s.z += y.z; s.w += y.w;
        }
        reinterpret_cast<float4*>(out)[i] = s;
    }
}

extern "C" void kernel_launch(void* const* d_in, const int* in_sizes, int n_in,
                              void* d_out, int out_size) {
    const float* q = (const float*)d_in[0];
    const float* k = (const float*)d_in[1];
    const float* v = (const float*)d_in[2];
    (void)in_sizes; (void)n_in; (void)out_size;
    const int n4 = BHN * SEQ * HD / 4;
    convert_kernel<<<(2 * n4) / 256, 256>>>(k, v);
    dim3 gridA(SEQ / BM, BHN, KS);
    rowsum_kernel<<<gridA, NTHREADS>>>(q);
    linv_kernel<<<(BHN * SEQ + 255) / 256, 256>>>();
    dim3 gridB(SEQ / BM, BHN, SPLIT);
    attn_kernel<<<gridB, NTHREADS>>>(q, (float*)d_out);
    reduce_kernel<<<(n4 + 255) / 256, 256>>>((float*)d_out);
}

// round 16
// speedup vs baseline: 1.0585x; 1.0046x over previous
#include <cuda_runtime.h>
#include <cuda_fp16.h>
#include <cstdint>

#define BHN 16
#define SEQ 4096
#define HD 64
#define BM 128
#define BN 64
#define NTHREADS 128
#define KPITCH 72   // smem row pitch in halves (144B rows -> conflict-free LDSM)
#define NT (SEQ / BN)
#define SPLIT 2
#define HT (NT / SPLIT)   // key-tiles per pass-B CTA
#define KS 4
#define RT (NT / KS)      // key-tiles per rowsum CTA
#define BMA 256           // rowsum rows per CTA (4 warps x 64 rows)
#define RF 4              // rowsum 16-row fragments per warp

// fp16 scratch copies of K and V (converted once per launch)
__device__ __half2 Ksc[BHN * SEQ * HD / 2];
__device__ __half2 Vsc[BHN * SEQ * HD / 2];
// rowsum partials and combined -log2(rowsum)
__device__ float RsP[KS * BHN * SEQ];
__device__ float LinvG[BHN * SEQ];
// partial O per key-split
__device__ float OPart[SPLIT * BHN * SEQ * HD];

__device__ __forceinline__ float ex2f(float x) {
    float y;
    asm("ex2.approx.f32 %0, %1;" : "=f"(y) : "f"(x));
    return y;
}

__device__ __forceinline__ uint32_t h2ex2(uint32_t x) {
    uint32_t y;
    asm("ex2.approx.f16x2 %0, %1;" : "=r"(y) : "r"(x));
    return y;
}

__device__ __forceinline__ uint32_t packh2(float a, float b) {
    __half2 t = __floats2half2_rn(a, b);
    return reinterpret_cast<uint32_t&>(t);
}

__device__ __forceinline__ uint32_t hadd2u(uint32_t a, uint32_t b) {
    __half2 r = __hadd2(reinterpret_cast<__half2&>(a), reinterpret_cast<__half2&>(b));
    return reinterpret_cast<uint32_t&>(r);
}

__device__ __forceinline__ void mma16816(float c[4], const uint32_t a[4],
                                         uint32_t b0, uint32_t b1) {
    asm volatile(
        "mma.sync.aligned.m16n8k16.row.col.f32.f16.f16.f32 "
        "{%0,%1,%2,%3},{%4,%5,%6,%7},{%8,%9},{%0,%1,%2,%3};"
        : "+f"(c[0]), "+f"(c[1]), "+f"(c[2]), "+f"(c[3])
        : "r"(a[0]), "r"(a[1]), "r"(a[2]), "r"(a[3]), "r"(b0), "r"(b1));
}

__device__ __forceinline__ void mma16816h(uint32_t c[2], const uint32_t a[4],
                                          uint32_t b0, uint32_t b1) {
    asm volatile(
        "mma.sync.aligned.m16n8k16.row.col.f16.f16.f16.f16 "
        "{%0,%1},{%2,%3,%4,%5},{%6,%7},{%0,%1};"
        : "+r"(c[0]), "+r"(c[1])
        : "r"(a[0]), "r"(a[1]), "r"(a[2]), "r"(a[3]), "r"(b0), "r"(b1));
}

__device__ __forceinline__ void ldsm_x4(uint32_t& r0, uint32_t& r1, uint32_t& r2,
                                        uint32_t& r3, uint32_t addr) {
    asm volatile("ldmatrix.sync.aligned.m8n8.x4.shared.b16 {%0,%1,%2,%3},[%4];"
                 : "=r"(r0), "=r"(r1), "=r"(r2), "=r"(r3) : "r"(addr));
}

__device__ __forceinline__ void ldsm_x4_t(uint32_t& r0, uint32_t& r1, uint32_t& r2,
                                          uint32_t& r3, uint32_t addr) {
    asm volatile("ldmatrix.sync.aligned.m8n8.x4.trans.shared.b16 {%0,%1,%2,%3},[%4];"
                 : "=r"(r0), "=r"(r1), "=r"(r2), "=r"(r3) : "r"(addr));
}

__device__ __forceinline__ void cpasync16(uint32_t dst, const void* src) {
    asm volatile("cp.async.cg.shared.global [%0],[%1],16;" :: "r"(dst), "l"(src));
}
__device__ __forceinline__ void cp_commit() {
    asm volatile("cp.async.commit_group;");
}
template <int N>
__device__ __forceinline__ void cp_wait() {
    asm volatile("cp.async.wait_group %0;" :: "n"(N));
}

// prefetch one [BN x HD] fp16 tile, rows permuted within each 16-key group.
__device__ __forceinline__ void prefetch_tile(uint32_t dstbase, const __half* src,
                                              int tid) {
#pragma unroll
    for (int t = 0; t < 4; ++t) {
        int i = tid + t * NTHREADS;
        int r = i >> 3;
        int c8 = (i & 7) << 3;
        int s = r & 15;
        int a = ((s & 6) << 1) | ((s & 8) >> 2) | (s & 1);
        int srcr = (r & 48) | a;
        cpasync16(dstbase + (uint32_t)((r * KPITCH + c8) * 2), src + srcr * HD + c8);
    }
}

// ---------------- pre-conversion kernel ----------------
__global__ void __launch_bounds__(256)
convert_kernel(const float* __restrict__ K, const float* __restrict__ V) {
    const int n4 = BHN * SEQ * HD / 4;
    int i = blockIdx.x * blockDim.x + threadIdx.x;
    if (i < n4) {
        float4 f = reinterpret_cast<const float4*>(K)[i];
        Ksc[2 * i] = __floats2half2_rn(f.x, f.y);
        Ksc[2 * i + 1] = __floats2half2_rn(f.z, f.w);
    } else {
        int j = i - n4;
        float4 f = reinterpret_cast<const float4*>(V)[j];
        Vsc[2 * j] = __floats2half2_rn(f.x, f.y);
        Vsc[2 * j + 1] = __floats2half2_rn(f.z, f.w);
    }
}

// ------- PASS A kernel: partial row sums, KS=4 key-split, 64 rows/warp --------
// 4 warps x 4 row-fragments: each LDSM'd K fragment feeds 4 MMA groups, halving
// per-row L1 wavefronts vs 32 rows/warp. No stores/O-regs -> fits 4 CTAs/SM.
__global__ void __launch_bounds__(NTHREADS, 4)
rowsum_kernel(const float* __restrict__ Qg) {
    __shared__ __half Kb[2][BN * KPITCH];

    const int bh = blockIdx.y;
    const int kz = blockIdx.z;
    const float* Qb = Qg + (size_t)bh * SEQ * HD;
    const __half* Kb16 = reinterpret_cast<const __half*>(Ksc) + (size_t)bh * SEQ * HD +
                         (size_t)kz * RT * BN * HD;

    const int tid = threadIdx.x;
    const int warp = tid >> 5;
    const int lane = tid & 31;
    const int g = lane >> 2;
    const int qq = lane & 3;
    const int row0 = blockIdx.x * BMA + warp * (16 * RF);

    const uint32_t bK0 = (uint32_t)__cvta_generic_to_shared(&Kb[0][0]);
    const uint32_t bK1 = (uint32_t)__cvta_generic_to_shared(&Kb[1][0]);

    const int qk_r = (lane & 7) + ((lane & 16) ? 8 : 0);
    const int qk_c = (lane & 8) ? 8 : 0;
    const uint32_t offK = (uint32_t)((qk_r * KPITCH + qk_c) * 2);
    const uint32_t NPOFF = 16 * KPITCH * 2;

    const float SC = 0.1803368801111244f;

    uint32_t qh[RF][4][4];
#pragma unroll
    for (int rf = 0; rf < RF; ++rf)
#pragma unroll
        for (int kc = 0; kc < 4; ++kc)
#pragma unroll
            for (int p = 0; p < 4; ++p) {
                int r = row0 + rf * 16 + g + (p & 1) * 8;
                int d = kc * 16 + (p >> 1) * 8 + qq * 2;
                float2 f = *reinterpret_cast<const float2*>(Qb + (size_t)r * HD + d);
                qh[rf][kc][p] = packh2(f.x * SC, f.y * SC);
            }

    float rs[RF][2] = {};
    prefetch_tile(bK0, Kb16, tid);
    cp_commit();
    for (int kt = 0; kt < RT; ++kt) {
        if (kt + 1 < RT) {
            prefetch_tile((kt & 1) ? bK0 : bK1, Kb16 + (size_t)(kt + 1) * BN * HD, tid);
            cp_commit();
            cp_wait<1>();
        } else {
            cp_wait<0>();
        }
        __syncthreads();
        const uint32_t aK = ((kt & 1) ? bK1 : bK0) + offK;
        uint32_t acc[RF][2] = {};
#pragma unroll
        for (int np = 0; np < 4; ++np) {
            uint32_t h[4][4];
#pragma unroll
            for (int kc = 0; kc < 4; ++kc)
                ldsm_x4(h[kc][0], h[kc][1], h[kc][2], h[kc][3],
                        aK + np * NPOFF + kc * 32);
#pragma unroll
            for (int rf = 0; rf < RF; ++rf) {
                uint32_t ca[2] = {0, 0}, cb[2] = {0, 0};
#pragma unroll
                for (int kc = 0; kc < 4; ++kc) {
                    mma16816h(ca, qh[rf][kc], h[kc][0], h[kc][1]);
                    mma16816h(cb, qh[rf][kc], h[kc][2], h[kc][3]);
                }
                acc[rf][0] = hadd2u(acc[rf][0], hadd2u(h2ex2(ca[0]), h2ex2(cb[0])));
                acc[rf][1] = hadd2u(acc[rf][1], hadd2u(h2ex2(ca[1]), h2ex2(cb[1])));
            }
        }
#pragma unroll
        for (int rf = 0; rf < RF; ++rf) {
            float2 f0 = __half22float2(reinterpret_cast<__half2&>(acc[rf][0]));
            float2 f1 = __half22float2(reinterpret_cast<__half2&>(acc[rf][1]));
            rs[rf][0] += f0.x + f0.y;
            rs[rf][1] += f1.x + f1.y;
        }
        __syncthreads();
    }
#pragma unroll
    for (int rf = 0; rf < RF; ++rf)
#pragma unroll
        for (int h = 0; h < 2; ++h) {
            float v = rs[rf][h];
            v += __shfl_xor_sync(0xffffffffu, v, 1);
            v += __shfl_xor_sync(0xffffffffu, v, 2);
            if (qq == 0)
                RsP[((size_t)kz * BHN + bh) * SEQ + row0 + rf * 16 + g + h * 8] = v;
        }
}

// ------------- combine KS partial rowsums into -log2(rowsum), fixed order -----
__global__ void __launch_bounds__(256)
linv_kernel() {
    const int n = BHN * SEQ;
    int i = blockIdx.x * blockDim.x + threadIdx.x;
    if (i < n) {
        float s = RsP[i];
#pragma unroll
        for (int p = 1; p < KS; ++p) s += RsP[i + p * n];
        LinvG[i] = -__log2f(s);
    }
}

// ---------------- PASS B kernel: key-split halves ----------
__global__ void __launch_bounds__(NTHREADS, 3)
attn_kernel(const float* __restrict__ Qg, float* __restrict__ out) {
    __shared__ __half Kb[2][BN * KPITCH];
    __shared__ __half Vb[2][BN * KPITCH];

    const int bh = blockIdx.y;
    const int kz = blockIdx.z;          // key-split index
    const int kt0 = kz * HT;
    const float* Qb = Qg + (size_t)bh * SEQ * HD;
    const __half* Kb16 = reinterpret_cast<const __half*>(Ksc) + (size_t)bh * SEQ * HD +
                         (size_t)kt0 * BN * HD;
    const __half* Vb16 = reinterpret_cast<const __half*>(Vsc) + (size_t)bh * SEQ * HD +
                         (size_t)kt0 * BN * HD;
    float* OPb = OPart + ((size_t)kz * BHN + bh) * SEQ * HD;
    float* Ab = out + (size_t)BHN * SEQ * HD + (size_t)bh * SEQ * SEQ;

    const int tid = threadIdx.x;
    const int warp = tid >> 5;
    const int lane = tid & 31;
    const int g = lane >> 2;
    const int qq = lane & 3;
    const int row0 = blockIdx.x * BM + warp * 32;

    const uint32_t bK0 = (uint32_t)__cvta_generic_to_shared(&Kb[0][0]);
    const uint32_t bK1 = (uint32_t)__cvta_generic_to_shared(&Kb[1][0]);
    const uint32_t bV0 = (uint32_t)__cvta_generic_to_shared(&Vb[0][0]);
    const uint32_t bV1 = (uint32_t)__cvta_generic_to_shared(&Vb[1][0]);

    const int qk_r = (lane & 7) + ((lane & 16) ? 8 : 0);
    const int qk_c = (lane & 8) ? 8 : 0;
    const uint32_t offK = (uint32_t)((qk_r * KPITCH + qk_c) * 2);
    const int v_r = (lane & 7) + ((lane & 8) ? 8 : 0);
    const int v_c = (lane & 16) ? 8 : 0;
    const uint32_t offV = (uint32_t)((v_r * KPITCH + v_c) * 2);
    const uint32_t NPOFF = 16 * KPITCH * 2;

    const float SC = 0.1803368801111244f;

    uint32_t qh[2][4][4];
#pragma unroll
    for (int rf = 0; rf < 2; ++rf)
#pragma unroll
        for (int kc = 0; kc < 4; ++kc)
#pragma unroll
            for (int p = 0; p < 4; ++p) {
                int r = row0 + rf * 16 + g + (p & 1) * 8;
                int d = kc * 16 + (p >> 1) * 8 + qq * 2;
                float2 f = *reinterpret_cast<const float2*>(Qb + (size_t)r * HD + d);
                qh[rf][kc][p] = packh2(f.x * SC, f.y * SC);
            }

    float linv[2][2];
#pragma unroll
    for (int rf = 0; rf < 2; ++rf)
#pragma unroll
        for (int h = 0; h < 2; ++h)
            linv[rf][h] = LinvG[bh * SEQ + row0 + rf * 16 + g + h * 8];

    float o[2][8][4] = {};
    prefetch_tile(bK0, Kb16, tid);
    prefetch_tile(bV0, Vb16, tid);
    cp_commit();
    for (int kt = 0; kt < HT; ++kt) {
        if (kt + 1 < HT) {
            const uint32_t dK = (kt & 1) ? bK0 : bK1;
            const uint32_t dV = (kt & 1) ? bV0 : bV1;
            prefetch_tile(dK, Kb16 + (size_t)(kt + 1) * BN * HD, tid);
            prefetch_tile(dV, Vb16 + (size_t)(kt + 1) * BN * HD, tid);
            cp_commit();
            cp_wait<1>();
        } else {
            cp_wait<0>();
        }
        __syncthreads();
        const uint32_t aK = ((kt & 1) ? bK1 : bK0) + offK;
        const uint32_t aV = ((kt & 1) ? bV1 : bV0) + offV;

#pragma unroll
        for (int np = 0; np < 4; ++np) {
            uint32_t h[4][4];
#pragma unroll
            for (int kc = 0; kc < 4; ++kc)
                ldsm_x4(h[kc][0], h[kc][1], h[kc][2], h[kc][3],
                        aK + np * NPOFF + kc * 32);
            float ca[2][4] = {}, cb[2][4] = {};
#pragma unroll
            for (int rf = 0; rf < 2; ++rf)
#pragma unroll
                for (int kc = 0; kc < 4; ++kc) {
                    mma16816(ca[rf], qh[rf][kc], h[kc][0], h[kc][1]);
                    mma16816(cb[rf], qh[rf][kc], h[kc][2], h[kc][3]);
                }

            uint32_t ah[2][4];
#pragma unroll
            for (int rf = 0; rf < 2; ++rf) {
                const float l0 = linv[rf][0], l1 = linv[rf][1];
                ca[rf][0] = ex2f(ca[rf][0] + l0);
                ca[rf][1] = ex2f(ca[rf][1] + l0);
                ca[rf][2] = ex2f(ca[rf][2] + l1);
                ca[rf][3] = ex2f(ca[rf][3] + l1);
                cb[rf][0] = ex2f(cb[rf][0] + l0);
                cb[rf][1] = ex2f(cb[rf][1] + l0);
                cb[rf][2] = ex2f(cb[rf][2] + l1);
                cb[rf][3] = ex2f(cb[rf][3] + l1);
                float* arow0 = Ab + (size_t)(row0 + rf * 16 + g) * SEQ +
                               (kt0 + kt) * BN + 16 * np + qq * 4;
                __stcs(reinterpret_cast<float4*>(arow0),
                       make_float4(ca[rf][0], ca[rf][1], cb[rf][0], cb[rf][1]));
                __stcs(reinterpret_cast<float4*>(arow0 + 8 * SEQ),
                       make_float4(ca[rf][2], ca[rf][3], cb[rf][2], cb[rf][3]));
                ah[rf][0] = packh2(ca[rf][0], ca[rf][1]);
                ah[rf][1] = packh2(ca[rf][2], ca[rf][3]);
                ah[rf][2] = packh2(cb[rf][0], cb[rf][1]);
                ah[rf][3] = packh2(cb[rf][2], cb[rf][3]);
            }

#pragma unroll
            for (int nd = 0; nd < 4; ++nd) {
                uint32_t v0, v1, v2, v3;
                ldsm_x4_t(v0, v1, v2, v3, aV + np * NPOFF + nd * 32);
#pragma unroll
                for (int rf = 0; rf < 2; ++rf) {
                    mma16816(o[rf][2 * nd], ah[rf], v0, v1);
                    mma16816(o[rf][2 * nd + 1], ah[rf], v2, v3);
                }
            }
        }
        __syncthreads();
    }

    // ---- write partial O ----
#pragma unroll
    for (int rf = 0; rf < 2; ++rf)
#pragma unroll
        for (int nt = 0; nt < 8; ++nt) {
            int col = nt * 8 + qq * 2;
            int r = row0 + rf * 16 + g;
            *reinterpret_cast<float2*>(OPb + (size_t)r * HD + col) =
                make_float2(o[rf][nt][0], o[rf][nt][1]);
            *reinterpret_cast<float2*>(OPb + (size_t)(r + 8) * HD + col) =
                make_float2(o[rf][nt][2], o[rf][nt][3]);
        }
}

// ---------------- O reduce: O = sum of SPLIT partials (fixed order) ----------
__global__ void __launch_bounds__(256)
reduce_kernel(float* __restrict__ out) {
    const int n4 = BHN * SEQ * HD / 4;
    int i = blockIdx.x * blockDim.x + threadIdx.x;
    if (i < n4) {
        const float4* a = reinterpret_cast<const float4*>(OPart);
        float4 s = a[i];
#pragma unroll
        for (int p = 1; p < SPLIT; ++p) {
            float4 y = a[i + (size_t)p * n4];
            s.x += y.x; s.y += y.y; s.z += y.z; s.w += y.w;
        }
        reinterpret_cast<float4*>(out)[i] = s;
    }
}

extern "C" void kernel_launch(void* const* d_in, const int* in_sizes, int n_in,
                              void* d_out, int out_size) {
    const float* q = (const float*)d_in[0];
    const float* k = (const float*)d_in[1];
    const float* v = (const float*)d_in[2];
    (void)in_sizes; (void)n_in; (void)out_size;
    const int n4 = BHN * SEQ * HD / 4;
    convert_kernel<<<(2 * n4) / 256, 256>>>(k, v);
    dim3 gridA(SEQ / BMA, BHN, KS);
    rowsum_kernel<<<gridA, NTHREADS>>>(q);
    linv_kernel<<<(BHN * SEQ + 255) / 256, 256>>>();
    dim3 gridB(SEQ / BM, BHN, SPLIT);
    attn_kernel<<<gridB, NTHREADS>>>(q, (float*)d_out);
    reduce_kernel<<<(n4 + 255) / 256, 256>>>((float*)d_out);
}